// round 1
// baseline (speedup 1.0000x reference)
#include <cuda_runtime.h>
#include <math_constants.h>

// SwinWindowAttention fused kernel.
// Shapes: B=32, nW=64 -> 2048 windows; N=49 tokens/window; C=128; H=4; hd=32.
// One CTA (256 threads) per window, everything fused through shared memory.
//
// d_in order (metadata): inputs, mask, qkv_w, qkv_b, proj_w, proj_b, rel_table
// out: float32 [B, nW, 7, 7, C] == [win][i][c]

#define WIN_TOTAL 2048
#define NTOK 49
#define CDIM 128
#define NHEAD 4
#define HDIM 32
#define C3 384
#define QS 388        /* qkv smem row stride in floats (388%32==4 -> conflict-free .128 patterns) */
#define PSS 52        /* prob smem row stride (16B-aligned rows) */

// shared memory layout (floats):
//   xs   : 49*128        = 6272     (x tile; reused as attention-out tile)
//   qk   : 49*388        = 19012    (qkv output, padded rows)
//   ws   : 16384                    (weight staging: qkv_w chunks, then proj_w)
//   ps   : 4*49*52       = 10192    (softmax probabilities)
//   relb : 676                      (relative position table, 169*4)
#define SM_XS   0
#define SM_QK   6272
#define SM_WS   (6272 + 19012)
#define SM_PS   (SM_WS + 16384)
#define SM_RELB (SM_PS + 10192)
#define SM_FLOATS (SM_RELB + 676)
#define SM_BYTES (SM_FLOATS * 4)

__global__ __launch_bounds__(256, 1)
void swin_win_attn_kernel(const float* __restrict__ xg_all,
                          const float* __restrict__ maskg,
                          const float* __restrict__ qkv_w,
                          const float* __restrict__ qkv_b,
                          const float* __restrict__ proj_w,
                          const float* __restrict__ proj_b,
                          const float* __restrict__ rel_table,
                          float* __restrict__ outg)
{
    extern __shared__ float sm[];
    float* xs   = sm + SM_XS;
    float* qk   = sm + SM_QK;
    float* ws   = sm + SM_WS;
    float* ps   = sm + SM_PS;
    float* relb = sm + SM_RELB;

    const int tid  = threadIdx.x;
    const int warp = tid >> 5;
    const int lane = tid & 31;
    const int win  = blockIdx.x;
    const int nw   = win & 63;

    // ---- load input tile + rel table ----
    {
        const float4* src = (const float4*)(xg_all + (size_t)win * (NTOK * CDIM));
        float4* dst = (float4*)xs;
        for (int i = tid; i < (NTOK * CDIM) / 4; i += 256) dst[i] = src[i];
        for (int i = tid; i < 676; i += 256) relb[i] = rel_table[i];
    }

    // qkv bias for this lane's 12 columns
    float qb[12];
    {
        const float4* b4 = (const float4*)(qkv_b + 12 * lane);
        float4 t0 = b4[0], t1 = b4[1], t2 = b4[2];
        qb[0]=t0.x; qb[1]=t0.y; qb[2]=t0.z; qb[3]=t0.w;
        qb[4]=t1.x; qb[5]=t1.y; qb[6]=t1.z; qb[7]=t1.w;
        qb[8]=t2.x; qb[9]=t2.y; qb[10]=t2.z; qb[11]=t2.w;
    }

    // ================= QKV GEMM: [49x128] @ [128x384] =================
    // warp w handles rows i = w, w+8, ..., (7 slots, clamp invalid)
    // lane handles columns [12*lane, 12*lane+12)
    float acc[7][12];
    #pragma unroll
    for (int r = 0; r < 7; ++r)
        #pragma unroll
        for (int j = 0; j < 12; ++j) acc[r][j] = 0.f;

    for (int c = 0; c < 4; ++c) {
        __syncthreads();
        // stage 32 rows of qkv_w (32x384 floats = 3072 float4)
        {
            const float4* src = (const float4*)qkv_w + c * 3072;
            float4* dst = (float4*)ws;
            #pragma unroll
            for (int t = 0; t < 12; ++t) dst[tid + t * 256] = src[tid + t * 256];
        }
        __syncthreads();
        const int k0 = 32 * c;
        #pragma unroll 2
        for (int kk = 0; kk < 32; ++kk) {
            float w12[12];
            {
                const float4* w4 = (const float4*)(ws + kk * C3 + 12 * lane);
                float4 a = w4[0], b = w4[1], d = w4[2];
                w12[0]=a.x; w12[1]=a.y; w12[2]=a.z; w12[3]=a.w;
                w12[4]=b.x; w12[5]=b.y; w12[6]=b.z; w12[7]=b.w;
                w12[8]=d.x; w12[9]=d.y; w12[10]=d.z; w12[11]=d.w;
            }
            #pragma unroll
            for (int r = 0; r < 7; ++r) {
                int i = warp + 8 * r; if (i > 48) i = 48;   // clamped dummy compute
                float xv = xs[i * CDIM + k0 + kk];
                #pragma unroll
                for (int j = 0; j < 12; ++j) acc[r][j] = fmaf(xv, w12[j], acc[r][j]);
            }
        }
    }
    // write qkv (+bias) to padded smem rows
    #pragma unroll
    for (int r = 0; r < 7; ++r) {
        int i = warp + 8 * r;
        if (i < NTOK) {
            float4* dst = (float4*)(qk + i * QS + 12 * lane);
            dst[0] = make_float4(acc[r][0]+qb[0],  acc[r][1]+qb[1],  acc[r][2]+qb[2],  acc[r][3]+qb[3]);
            dst[1] = make_float4(acc[r][4]+qb[4],  acc[r][5]+qb[5],  acc[r][6]+qb[6],  acc[r][7]+qb[7]);
            dst[2] = make_float4(acc[r][8]+qb[8],  acc[r][9]+qb[9],  acc[r][10]+qb[10],acc[r][11]+qb[11]);
        }
    }
    __syncthreads();

    // stage proj_w into ws (128x128 floats = 4096 float4); consumed after next barrier
    {
        const float4* src = (const float4*)proj_w;
        float4* dst = (float4*)ws;
        #pragma unroll
        for (int t = 0; t < 16; ++t) dst[tid + t * 256] = src[tid + t * 256];
    }

    // ================= attention scores + softmax =================
    const float scale = 0.17677669529663687f;   // 32^-0.5
    const float NEG_INF = -CUDART_INF_F;
    for (int m = warp; m < NHEAD * NTOK; m += 8) {
        const int h = m / NTOK;
        const int i = m - h * NTOK;
        float qr[32];
        {
            const float4* q4 = (const float4*)(qk + i * QS + HDIM * h);
            #pragma unroll
            for (int d = 0; d < 8; ++d) {
                float4 t = q4[d];
                qr[4*d]=t.x*scale; qr[4*d+1]=t.y*scale; qr[4*d+2]=t.z*scale; qr[4*d+3]=t.w*scale;
            }
        }
        const float* mg = maskg + nw * (NTOK * NTOK) + i * NTOK;
        const int iy = i / 7, ix = i - 7 * (i / 7);

        // j0 = lane (always valid)
        float s0;
        {
            const int j = lane;
            const float4* k4 = (const float4*)(qk + j * QS + CDIM + HDIM * h);
            float d0 = 0.f;
            #pragma unroll
            for (int d = 0; d < 8; ++d) {
                float4 t = k4[d];
                d0 = fmaf(qr[4*d],   t.x, d0);
                d0 = fmaf(qr[4*d+1], t.y, d0);
                d0 = fmaf(qr[4*d+2], t.z, d0);
                d0 = fmaf(qr[4*d+3], t.w, d0);
            }
            const int jy = j / 7, jx = j - 7 * jy;
            s0 = d0 + relb[((iy - jy + 6) * 13 + (ix - jx + 6)) * 4 + h] + mg[j];
        }
        // j1 = lane + 32 (valid for lane < 17)
        float s1 = NEG_INF;
        if (lane < 17) {
            const int j = lane + 32;
            const float4* k4 = (const float4*)(qk + j * QS + CDIM + HDIM * h);
            float d1 = 0.f;
            #pragma unroll
            for (int d = 0; d < 8; ++d) {
                float4 t = k4[d];
                d1 = fmaf(qr[4*d],   t.x, d1);
                d1 = fmaf(qr[4*d+1], t.y, d1);
                d1 = fmaf(qr[4*d+2], t.z, d1);
                d1 = fmaf(qr[4*d+3], t.w, d1);
            }
            const int jy = j / 7, jx = j - 7 * jy;
            s1 = d1 + relb[((iy - jy + 6) * 13 + (ix - jx + 6)) * 4 + h] + mg[j];
        }
        // softmax across the 49 entries spread over lanes
        float mx = fmaxf(s0, s1);
        #pragma unroll
        for (int o = 16; o; o >>= 1) mx = fmaxf(mx, __shfl_xor_sync(0xffffffffu, mx, o));
        float e0 = __expf(s0 - mx);
        float e1 = (lane < 17) ? __expf(s1 - mx) : 0.f;
        float sum = e0 + e1;
        #pragma unroll
        for (int o = 16; o; o >>= 1) sum += __shfl_xor_sync(0xffffffffu, sum, o);
        const float inv = 1.0f / sum;
        float* pr = ps + (h * NTOK + i) * PSS;
        pr[lane] = e0 * inv;
        if (lane < 17) pr[lane + 32] = e1 * inv;
    }
    __syncthreads();

    // ================= attn @ V  -> ao (reuse xs) =================
    // lane owns column c = 32h + lane for h = 0..3; warp owns its 7 rows.
    float av[7][4];
    #pragma unroll
    for (int r = 0; r < 7; ++r)
        #pragma unroll
        for (int h = 0; h < 4; ++h) av[r][h] = 0.f;

    for (int j = 0; j < 48; j += 4) {
        float vv[4][4];
        #pragma unroll
        for (int q = 0; q < 4; ++q)
            #pragma unroll
            for (int h = 0; h < 4; ++h)
                vv[q][h] = qk[(j + q) * QS + 2 * CDIM + HDIM * h + lane];
        #pragma unroll
        for (int r = 0; r < 7; ++r) {
            int i = warp + 8 * r; if (i > 48) i = 48;
            #pragma unroll
            for (int h = 0; h < 4; ++h) {
                float4 p4 = *(const float4*)(ps + (h * NTOK + i) * PSS + j);
                av[r][h] = fmaf(p4.x, vv[0][h], av[r][h]);
                av[r][h] = fmaf(p4.y, vv[1][h], av[r][h]);
                av[r][h] = fmaf(p4.z, vv[2][h], av[r][h]);
                av[r][h] = fmaf(p4.w, vv[3][h], av[r][h]);
            }
        }
    }
    { // j = 48 remainder
        float vv[4];
        #pragma unroll
        for (int h = 0; h < 4; ++h) vv[h] = qk[48 * QS + 2 * CDIM + HDIM * h + lane];
        #pragma unroll
        for (int r = 0; r < 7; ++r) {
            int i = warp + 8 * r; if (i > 48) i = 48;
            #pragma unroll
            for (int h = 0; h < 4; ++h)
                av[r][h] = fmaf(ps[(h * NTOK + i) * PSS + 48], vv[h], av[r][h]);
        }
    }
    // store attention output into xs (x tile is dead)
    #pragma unroll
    for (int r = 0; r < 7; ++r) {
        int i = warp + 8 * r;
        if (i < NTOK) {
            #pragma unroll
            for (int h = 0; h < 4; ++h)
                xs[i * CDIM + HDIM * h + lane] = av[r][h];
        }
    }
    __syncthreads();   // also guarantees proj_w staging is complete

    // ================= projection: [49x128] @ [128x128] + bias =================
    float po[7][4];
    #pragma unroll
    for (int r = 0; r < 7; ++r)
        #pragma unroll
        for (int j = 0; j < 4; ++j) po[r][j] = 0.f;

    #pragma unroll 2
    for (int k = 0; k < CDIM; ++k) {
        float4 w4 = *(const float4*)(ws + k * CDIM + 4 * lane);
        #pragma unroll
        for (int r = 0; r < 7; ++r) {
            int i = warp + 8 * r; if (i > 48) i = 48;
            float a = xs[i * CDIM + k];
            po[r][0] = fmaf(a, w4.x, po[r][0]);
            po[r][1] = fmaf(a, w4.y, po[r][1]);
            po[r][2] = fmaf(a, w4.z, po[r][2]);
            po[r][3] = fmaf(a, w4.w, po[r][3]);
        }
    }
    {
        const float4 pb4 = *(const float4*)(proj_b + 4 * lane);
        float* og = outg + (size_t)win * (NTOK * CDIM);
        #pragma unroll
        for (int r = 0; r < 7; ++r) {
            int i = warp + 8 * r;
            if (i < NTOK) {
                float4 v = make_float4(po[r][0] + pb4.x, po[r][1] + pb4.y,
                                       po[r][2] + pb4.z, po[r][3] + pb4.w);
                *(float4*)(og + i * CDIM + 4 * lane) = v;
            }
        }
    }
}

extern "C" void kernel_launch(void* const* d_in, const int* in_sizes, int n_in,
                              void* d_out, int out_size)
{
    const float* x      = (const float*)d_in[0];
    const float* mask   = (const float*)d_in[1];
    const float* qkv_w  = (const float*)d_in[2];
    const float* qkv_b  = (const float*)d_in[3];
    const float* proj_w = (const float*)d_in[4];
    const float* proj_b = (const float*)d_in[5];
    const float* relt   = (const float*)d_in[6];
    float* out = (float*)d_out;

    cudaFuncSetAttribute(swin_win_attn_kernel,
                         cudaFuncAttributeMaxDynamicSharedMemorySize, SM_BYTES);
    swin_win_attn_kernel<<<WIN_TOTAL, 256, SM_BYTES>>>(
        x, mask, qkv_w, qkv_b, proj_w, proj_b, relt, out);
}

// round 2
// speedup vs baseline: 1.0602x; 1.0602x over previous
#include <cuda_runtime.h>
#include <math_constants.h>

// SwinWindowAttention fused kernel, round 2: packed fma.rn.f32x2 math.
// Shapes: 2048 windows; N=49 tokens; C=128; H=4; hd=32. One CTA/window, 256 thr.

#define WIN_TOTAL 2048
#define NTOK 49
#define CDIM 128
#define NHEAD 4
#define HDIM 32
#define C3 384
#define QS 388        /* qkv smem row stride (floats) */
#define PSS 52        /* prob smem row stride */

#define SM_XS   0
#define SM_QK   6272
#define SM_WS   (6272 + 19012)
#define SM_PS   (SM_WS + 16384)
#define SM_RELB (SM_PS + 10192)
#define SM_MS   (SM_RELB + 676)
#define SM_FLOATS (SM_MS + 2401)
#define SM_BYTES (SM_FLOATS * 4)

typedef unsigned long long u64;

__device__ __forceinline__ void fma2(u64& d, u64 a, u64 b) {
    asm("fma.rn.f32x2 %0, %1, %2, %0;" : "+l"(d) : "l"(a), "l"(b));
}
__device__ __forceinline__ u64 bcast2(float x) {
    u64 r; asm("mov.b64 %0, {%1, %1};" : "=l"(r) : "f"(x)); return r;
}
__device__ __forceinline__ float2 unpack2(u64 v) {
    float2 r; asm("mov.b64 {%0, %1}, %2;" : "=f"(r.x), "=f"(r.y) : "l"(v)); return r;
}

__global__ __launch_bounds__(256, 1)
void swin_win_attn_kernel(const float* __restrict__ xg_all,
                          const float* __restrict__ maskg,
                          const float* __restrict__ qkv_w,
                          const float* __restrict__ qkv_b,
                          const float* __restrict__ proj_w,
                          const float* __restrict__ proj_b,
                          const float* __restrict__ rel_table,
                          float* __restrict__ outg)
{
    extern __shared__ float sm[];
    float* xs   = sm + SM_XS;
    float* qk   = sm + SM_QK;
    float* ws   = sm + SM_WS;
    float* ps   = sm + SM_PS;
    float* relb = sm + SM_RELB;
    float* ms   = sm + SM_MS;

    const int tid  = threadIdx.x;
    const int warp = tid >> 5;
    const int lane = tid & 31;
    const int win  = blockIdx.x;
    const int nw   = win & 63;

    // ---- load input tile, rel table, shift mask ----
    {
        const float4* src = (const float4*)(xg_all + (size_t)win * (NTOK * CDIM));
        float4* dst = (float4*)xs;
        for (int i = tid; i < (NTOK * CDIM) / 4; i += 256) dst[i] = src[i];
        for (int i = tid; i < 676; i += 256) relb[i] = rel_table[i];
        const float* mgsrc = maskg + nw * (NTOK * NTOK);
        for (int i = tid; i < NTOK * NTOK; i += 256) ms[i] = mgsrc[i];
    }

    // qkv bias for this lane's 12 columns
    float qb[12];
    {
        const float4* b4 = (const float4*)(qkv_b + 12 * lane);
        float4 t0 = b4[0], t1 = b4[1], t2 = b4[2];
        qb[0]=t0.x; qb[1]=t0.y; qb[2]=t0.z; qb[3]=t0.w;
        qb[4]=t1.x; qb[5]=t1.y; qb[6]=t1.z; qb[7]=t1.w;
        qb[8]=t2.x; qb[9]=t2.y; qb[10]=t2.z; qb[11]=t2.w;
    }

    // ================= QKV GEMM: [49x128] @ [128x384], packed f32x2 =========
    u64 acc2[7][6];
    #pragma unroll
    for (int r = 0; r < 7; ++r)
        #pragma unroll
        for (int j = 0; j < 6; ++j) acc2[r][j] = 0ull;

    for (int c = 0; c < 4; ++c) {
        __syncthreads();
        {   // stage 32 rows of qkv_w (3072 float4)
            const float4* src = (const float4*)qkv_w + c * 3072;
            float4* dst = (float4*)ws;
            #pragma unroll
            for (int t = 0; t < 12; ++t) dst[tid + t * 256] = src[tid + t * 256];
        }
        __syncthreads();
        const int k0 = 32 * c;
        #pragma unroll 4
        for (int kk = 0; kk < 32; ++kk) {
            u64 w6[6];
            {
                const ulonglong2* w2 = (const ulonglong2*)(ws + kk * C3 + 12 * lane);
                ulonglong2 a = w2[0], b = w2[1], d = w2[2];
                w6[0]=a.x; w6[1]=a.y; w6[2]=b.x; w6[3]=b.y; w6[4]=d.x; w6[5]=d.y;
            }
            #pragma unroll
            for (int r = 0; r < 7; ++r) {
                int i = warp + 8 * r; if (i > 48) i = 48;   // clamped dummy compute
                u64 x2 = bcast2(xs[i * CDIM + k0 + kk]);
                #pragma unroll
                for (int j = 0; j < 6; ++j) fma2(acc2[r][j], x2, w6[j]);
            }
        }
    }
    // write qkv (+bias) to padded smem rows
    #pragma unroll
    for (int r = 0; r < 7; ++r) {
        int i = warp + 8 * r;
        if (i < NTOK) {
            float4* dst = (float4*)(qk + i * QS + 12 * lane);
            float2 p0 = unpack2(acc2[r][0]), p1 = unpack2(acc2[r][1]);
            float2 p2 = unpack2(acc2[r][2]), p3 = unpack2(acc2[r][3]);
            float2 p4 = unpack2(acc2[r][4]), p5 = unpack2(acc2[r][5]);
            dst[0] = make_float4(p0.x+qb[0], p0.y+qb[1], p1.x+qb[2], p1.y+qb[3]);
            dst[1] = make_float4(p2.x+qb[4], p2.y+qb[5], p3.x+qb[6], p3.y+qb[7]);
            dst[2] = make_float4(p4.x+qb[8], p4.y+qb[9], p5.x+qb[10], p5.y+qb[11]);
        }
    }
    __syncthreads();

    // stage proj_w into ws (4096 float4); consumed after next barrier
    {
        const float4* src = (const float4*)proj_w;
        float4* dst = (float4*)ws;
        #pragma unroll
        for (int t = 0; t < 16; ++t) dst[tid + t * 256] = src[tid + t * 256];
    }

    // ================= attention scores + softmax (packed dots) =============
    const float scale = 0.17677669529663687f;   // 32^-0.5
    const float NEG_INF = -CUDART_INF_F;
    for (int m = warp; m < NHEAD * NTOK; m += 8) {
        const int h = m / NTOK;
        const int i = m - h * NTOK;
        u64 qr2[16];
        {
            const ulonglong2* q2 = (const ulonglong2*)(qk + i * QS + HDIM * h);
            #pragma unroll
            for (int d = 0; d < 8; ++d) {
                ulonglong2 t = q2[d];
                qr2[2*d] = t.x; qr2[2*d+1] = t.y;
            }
        }
        const float* mrow = ms + i * NTOK;
        const int iy = i / 7, ix = i - 7 * (i / 7);

        // j0 = lane (always valid)
        float s0;
        {
            const int j = lane;
            const ulonglong2* k2 = (const ulonglong2*)(qk + j * QS + CDIM + HDIM * h);
            u64 da = 0ull, db = 0ull;
            #pragma unroll
            for (int d = 0; d < 8; ++d) {
                ulonglong2 t = k2[d];
                fma2(da, qr2[2*d],   t.x);
                fma2(db, qr2[2*d+1], t.y);
            }
            float2 fa = unpack2(da), fb = unpack2(db);
            float dot = (fa.x + fa.y) + (fb.x + fb.y);
            const int jy = j / 7, jx = j - 7 * jy;
            s0 = fmaf(dot, scale, relb[((iy - jy + 6) * 13 + (ix - jx + 6)) * 4 + h] + mrow[j]);
        }
        // j1 = lane + 32 (valid for lane < 17)
        float s1 = NEG_INF;
        if (lane < 17) {
            const int j = lane + 32;
            const ulonglong2* k2 = (const ulonglong2*)(qk + j * QS + CDIM + HDIM * h);
            u64 da = 0ull, db = 0ull;
            #pragma unroll
            for (int d = 0; d < 8; ++d) {
                ulonglong2 t = k2[d];
                fma2(da, qr2[2*d],   t.x);
                fma2(db, qr2[2*d+1], t.y);
            }
            float2 fa = unpack2(da), fb = unpack2(db);
            float dot = (fa.x + fa.y) + (fb.x + fb.y);
            const int jy = j / 7, jx = j - 7 * jy;
            s1 = fmaf(dot, scale, relb[((iy - jy + 6) * 13 + (ix - jx + 6)) * 4 + h] + mrow[j]);
        }
        // softmax across the 49 entries spread over lanes
        float mx = fmaxf(s0, s1);
        #pragma unroll
        for (int o = 16; o; o >>= 1) mx = fmaxf(mx, __shfl_xor_sync(0xffffffffu, mx, o));
        float e0 = __expf(s0 - mx);
        float e1 = (lane < 17) ? __expf(s1 - mx) : 0.f;
        float sum = e0 + e1;
        #pragma unroll
        for (int o = 16; o; o >>= 1) sum += __shfl_xor_sync(0xffffffffu, sum, o);
        const float inv = 1.0f / sum;
        float* pr = ps + (h * NTOK + i) * PSS;
        pr[lane] = e0 * inv;
        if (lane < 17) pr[lane + 32] = e1 * inv;
    }
    __syncthreads();

    // ================= attn @ V -> xs (scalar fp32; ~8% of flops) ===========
    float av[7][4];
    #pragma unroll
    for (int r = 0; r < 7; ++r)
        #pragma unroll
        for (int h = 0; h < 4; ++h) av[r][h] = 0.f;

    for (int j = 0; j < 48; j += 4) {
        float vv[4][4];
        #pragma unroll
        for (int q = 0; q < 4; ++q)
            #pragma unroll
            for (int h = 0; h < 4; ++h)
                vv[q][h] = qk[(j + q) * QS + 2 * CDIM + HDIM * h + lane];
        #pragma unroll
        for (int r = 0; r < 7; ++r) {
            int i = warp + 8 * r; if (i > 48) i = 48;
            #pragma unroll
            for (int h = 0; h < 4; ++h) {
                float4 p4 = *(const float4*)(ps + (h * NTOK + i) * PSS + j);
                av[r][h] = fmaf(p4.x, vv[0][h], av[r][h]);
                av[r][h] = fmaf(p4.y, vv[1][h], av[r][h]);
                av[r][h] = fmaf(p4.z, vv[2][h], av[r][h]);
                av[r][h] = fmaf(p4.w, vv[3][h], av[r][h]);
            }
        }
    }
    { // j = 48 remainder
        float vv[4];
        #pragma unroll
        for (int h = 0; h < 4; ++h) vv[h] = qk[48 * QS + 2 * CDIM + HDIM * h + lane];
        #pragma unroll
        for (int r = 0; r < 7; ++r) {
            int i = warp + 8 * r; if (i > 48) i = 48;
            #pragma unroll
            for (int h = 0; h < 4; ++h)
                av[r][h] = fmaf(ps[(h * NTOK + i) * PSS + 48], vv[h], av[r][h]);
        }
    }
    #pragma unroll
    for (int r = 0; r < 7; ++r) {
        int i = warp + 8 * r;
        if (i < NTOK) {
            #pragma unroll
            for (int h = 0; h < 4; ++h)
                xs[i * CDIM + HDIM * h + lane] = av[r][h];
        }
    }
    __syncthreads();   // also guarantees proj_w staging is complete

    // ================= projection: [49x128] @ [128x128], packed f32x2 =======
    u64 po2[7][2];
    #pragma unroll
    for (int r = 0; r < 7; ++r) { po2[r][0] = 0ull; po2[r][1] = 0ull; }

    #pragma unroll 4
    for (int k = 0; k < CDIM; ++k) {
        ulonglong2 w2 = *(const ulonglong2*)(ws + k * CDIM + 4 * lane);
        #pragma unroll
        for (int r = 0; r < 7; ++r) {
            int i = warp + 8 * r; if (i > 48) i = 48;
            u64 a2 = bcast2(xs[i * CDIM + k]);
            fma2(po2[r][0], a2, w2.x);
            fma2(po2[r][1], a2, w2.y);
        }
    }
    {
        const float4 pb4 = *(const float4*)(proj_b + 4 * lane);
        float* og = outg + (size_t)win * (NTOK * CDIM);
        #pragma unroll
        for (int r = 0; r < 7; ++r) {
            int i = warp + 8 * r;
            if (i < NTOK) {
                float2 a = unpack2(po2[r][0]), b = unpack2(po2[r][1]);
                float4 v = make_float4(a.x + pb4.x, a.y + pb4.y, b.x + pb4.z, b.y + pb4.w);
                *(float4*)(og + i * CDIM + 4 * lane) = v;
            }
        }
    }
}

extern "C" void kernel_launch(void* const* d_in, const int* in_sizes, int n_in,
                              void* d_out, int out_size)
{
    const float* x      = (const float*)d_in[0];
    const float* mask   = (const float*)d_in[1];
    const float* qkv_w  = (const float*)d_in[2];
    const float* qkv_b  = (const float*)d_in[3];
    const float* proj_w = (const float*)d_in[4];
    const float* proj_b = (const float*)d_in[5];
    const float* relt   = (const float*)d_in[6];
    float* out = (float*)d_out;

    cudaFuncSetAttribute(swin_win_attn_kernel,
                         cudaFuncAttributeMaxDynamicSharedMemorySize, SM_BYTES);
    swin_win_attn_kernel<<<WIN_TOTAL, 256, SM_BYTES>>>(
        x, mask, qkv_w, qkv_b, proj_w, proj_b, relt, out);
}